// round 2
// baseline (speedup 1.0000x reference)
#include <cuda_runtime.h>
#include <math.h>

#define HH 512
#define WW 512
#define PLANE (512*512)
#define SHAPE_OFF (1*PLANE)
#define SIZE_OFF  (1025*PLANE)
#define HEAT_OFF  (1027*PLANE)
#define NPTS 10
#define MM 128
#define BLKS_PER_HM 64

// per-block partial argmax results (written every run, no init needed)
__device__ unsigned long long g_partial[NPTS][BLKS_PER_HM];
// per-heatmap arrival counters; self-resetting (last block writes 0 back)
__device__ unsigned int g_count[NPTS];

__device__ __forceinline__ unsigned int fkey(float v) {
    unsigned int b = __float_as_uint(v);
    return (b & 0x80000000u) ? ~b : (b | 0x80000000u);
}

// One kernel: 640 blocks (64 per heatmap) x 256 threads.
// Phase 1: each block reduces its 16KB chunk of its heatmap -> partial slot.
// Phase 2: last-arriving block per heatmap reduces 64 partials and computes
//          the full 128x128 output for that point.
__global__ void fused_kernel(const float* __restrict__ feat,
                             float* __restrict__ out) {
    __shared__ unsigned long long s_red[256];
    __shared__ float s_vec[1024];        // 32x32 shape vector
    __shared__ float s_rows[MM * 32];    // y-interpolated rows (16KB)
    __shared__ unsigned int s_isLast;

    int hm    = blockIdx.x >> 6;
    int chunk = blockIdx.x & 63;
    const float* heat = feat + HEAT_OFF + (size_t)hm * PLANE;
    int base = chunk * 4096;

    // ---- phase 1: chunk argmax (float4, 16 elems/thread) ----
    unsigned long long best = 0ULL;
#pragma unroll
    for (int j = 0; j < 4; j++) {
        int e = base + ((j * 256 + threadIdx.x) << 2);
        float4 v = *reinterpret_cast<const float4*>(heat + e);
        float vals[4] = {v.x, v.y, v.z, v.w};
#pragma unroll
        for (int m = 0; m < 4; m++) {
            unsigned long long p =
                ((unsigned long long)fkey(vals[m]) << 32) |
                (unsigned int)(~(unsigned int)(e + m));
            best = (p > best) ? p : best;
        }
    }
    s_red[threadIdx.x] = best;
    __syncthreads();
#pragma unroll
    for (int stride = 128; stride > 0; stride >>= 1) {
        if (threadIdx.x < stride) {
            unsigned long long o = s_red[threadIdx.x + stride];
            if (o > s_red[threadIdx.x]) s_red[threadIdx.x] = o;
        }
        __syncthreads();
    }

    if (threadIdx.x == 0) {
        g_partial[hm][chunk] = s_red[0];
        __threadfence();
        unsigned int prev = atomicAdd(&g_count[hm], 1u);
        s_isLast = (prev == BLKS_PER_HM - 1) ? 1u : 0u;
    }
    __syncthreads();
    if (!s_isLast) return;

    // ---- phase 2: last block for this heatmap ----
    __threadfence();  // make other blocks' partial writes visible

    // reduce 64 partials
    if (threadIdx.x < 64) s_red[threadIdx.x] = g_partial[hm][threadIdx.x];
    __syncthreads();
#pragma unroll
    for (int stride = 32; stride > 0; stride >>= 1) {
        if (threadIdx.x < stride) {
            unsigned long long o = s_red[threadIdx.x + stride];
            if (o > s_red[threadIdx.x]) s_red[threadIdx.x] = o;
        }
        __syncthreads();
    }
    unsigned long long packed = s_red[0];
    int idx = (int)(~(unsigned int)(packed & 0xFFFFFFFFu));
    int py = idx >> 9;
    int px = idx & 511;

    // reset counter for next graph replay (only this block touches it now)
    if (threadIdx.x == 0) g_count[hm] = 0u;

    float hv = fabsf(feat[SIZE_OFF + py * WW + px]);
    float wv = fabsf(feat[SIZE_OFF + PLANE + py * WW + px]);
    int h = min(max((int)hv, 1), MM);
    int w = min(max((int)wv, 1), MM);
    float hf = (float)h, wf = (float)w;

    // gather 1024 scattered channel values (stride 1MB)
    for (int c = threadIdx.x; c < 1024; c += 256)
        s_vec[c] = feat[SHAPE_OFF + (size_t)c * PLANE + py * WW + px];
    __syncthreads();

    // y-interp: all 128 rows x 32 cols
    for (int i = threadIdx.x; i < MM * 32; i += 256) {
        int r = i >> 5;
        int x = i & 31;
        float sy = ((float)r + 0.5f) * 32.0f / hf - 0.5f;
        sy = fminf(fmaxf(sy, 0.0f), 31.0f);
        int y0 = (int)floorf(sy);
        int y1 = min(y0 + 1, 31);
        float wy = sy - (float)y0;
        s_rows[i] = s_vec[y0 * 32 + x] * (1.0f - wy) + s_vec[y1 * 32 + x] * wy;
    }
    __syncthreads();

    const float* sal = feat;  // channel 0
    float* o = out + (size_t)hm * (MM * MM);
    int h2 = h >> 1, w2 = w >> 1;

    // 16384 outputs, 64 per thread
    for (int i = threadIdx.x; i < MM * MM; i += 256) {
        int r = i >> 7;
        int c = i & 127;
        float sx = ((float)c + 0.5f) * 32.0f / wf - 0.5f;
        sx = fminf(fmaxf(sx, 0.0f), 31.0f);
        int x0 = (int)floorf(sx);
        int x1 = min(x0 + 1, 31);
        float wx = sx - (float)x0;
        float v = s_rows[r * 32 + x0] * (1.0f - wx) +
                  s_rows[r * 32 + x1] * wx;
        float lv = 1.0f / (1.0f + __expf(-v));
        int gr = py - h2 + r;
        int gc = px - w2 + c;
        bool valid = (r < h) && (c < w) &&
                     (gr >= 0) && (gr < HH) && (gc >= 0) && (gc < WW);
        float s = valid ? sal[gr * WW + gc] : 0.0f;
        o[i] = valid ? lv * s : 0.0f;
    }
}

extern "C" void kernel_launch(void* const* d_in, const int* in_sizes, int n_in,
                              void* d_out, int out_size) {
    const float* feat = (const float*)d_in[0];
    float* out = (float*)d_out;
    fused_kernel<<<NPTS * BLKS_PER_HM, 256>>>(feat, out);
}

// round 3
// speedup vs baseline: 2.3469x; 2.3469x over previous
#include <cuda_runtime.h>
#include <math.h>

#define HH 512
#define WW 512
#define PLANE (512*512)
#define SHAPE_OFF (1*PLANE)
#define SIZE_OFF  (1025*PLANE)
#define HEAT_OFF  (1027*PLANE)
#define NPTS 10
#define MM 128
#define BLKS_PER_HM 64

// per-block partial argmax results; every slot written every run -> no init
__device__ unsigned long long g_partial[NPTS][BLKS_PER_HM];

__device__ __forceinline__ unsigned int fkey(float v) {
    unsigned int b = __float_as_uint(v);
    return (b & 0x80000000u) ? ~b : (b | 0x80000000u);
}

__device__ __forceinline__ unsigned long long umax64(unsigned long long a,
                                                     unsigned long long b) {
    return a > b ? a : b;
}

// 640 blocks (64/heatmap) x 256 threads; 16 floats/thread via float4.
__global__ void argmax_kernel(const float* __restrict__ feat) {
    int hm    = blockIdx.x >> 6;
    int chunk = blockIdx.x & 63;
    const float* heat = feat + HEAT_OFF + (size_t)hm * PLANE;
    int base = chunk * 4096;

    unsigned long long best = 0ULL;
#pragma unroll
    for (int j = 0; j < 4; j++) {
        int e = base + ((j * 256 + threadIdx.x) << 2);
        float4 v = *reinterpret_cast<const float4*>(heat + e);
        float vals[4] = {v.x, v.y, v.z, v.w};
#pragma unroll
        for (int m = 0; m < 4; m++) {
            unsigned long long p =
                ((unsigned long long)fkey(vals[m]) << 32) |
                (unsigned int)(~(unsigned int)(e + m));
            best = umax64(best, p);
        }
    }

    // warp reduce
#pragma unroll
    for (int off = 16; off > 0; off >>= 1)
        best = umax64(best, __shfl_xor_sync(0xFFFFFFFFu, best, off));

    __shared__ unsigned long long s[8];
    if ((threadIdx.x & 31) == 0) s[threadIdx.x >> 5] = best;
    __syncthreads();
    if (threadIdx.x < 32) {
        unsigned long long v = (threadIdx.x < 8) ? s[threadIdx.x] : 0ULL;
#pragma unroll
        for (int off = 4; off > 0; off >>= 1)
            v = umax64(v, __shfl_xor_sync(0xFFFFFFFFu, v, off));
        if (threadIdx.x == 0) g_partial[hm][chunk] = v;
    }
}

// grid (NPTS, 8): each block computes 16 output rows of one point. 256 threads.
__global__ void compute_kernel(const float* __restrict__ feat,
                               float* __restrict__ out) {
    __shared__ float s_vec[1024];       // 32x32 shape vector
    __shared__ float s_rows[16 * 32];   // y-interpolated rows for this slice
    __shared__ unsigned long long s_red[64];

    int pt = blockIdx.x;
    int r0 = blockIdx.y * 16;

    // reduce the 64 partials (cheap: L2-resident)
    if (threadIdx.x < 64) s_red[threadIdx.x] = g_partial[pt][threadIdx.x];
    __syncthreads();
    if (threadIdx.x < 32) {
        unsigned long long v = umax64(s_red[threadIdx.x], s_red[threadIdx.x + 32]);
#pragma unroll
        for (int off = 16; off > 0; off >>= 1)
            v = umax64(v, __shfl_xor_sync(0xFFFFFFFFu, v, off));
        if (threadIdx.x == 0) s_red[0] = v;
    }
    __syncthreads();

    int idx = (int)(~(unsigned int)(s_red[0] & 0xFFFFFFFFu));
    int py = idx >> 9;
    int px = idx & 511;

    float hv = fabsf(feat[SIZE_OFF + py * WW + px]);
    float wv = fabsf(feat[SIZE_OFF + PLANE + py * WW + px]);
    int h = min(max((int)hv, 1), MM);
    int w = min(max((int)wv, 1), MM);
    float hf = (float)h, wf = (float)w;

    // gather 1024 scattered channel values (stride 1MB); 4/thread, independent
    for (int c = threadIdx.x; c < 1024; c += 256)
        s_vec[c] = feat[SHAPE_OFF + (size_t)c * PLANE + py * WW + px];
    __syncthreads();

    // y-interp for our 16 rows
    for (int i = threadIdx.x; i < 16 * 32; i += 256) {
        int r = r0 + (i >> 5);
        int x = i & 31;
        float sy = ((float)r + 0.5f) * 32.0f / hf - 0.5f;
        sy = fminf(fmaxf(sy, 0.0f), 31.0f);
        int y0 = (int)floorf(sy);
        int y1 = min(y0 + 1, 31);
        float wy = sy - (float)y0;
        s_rows[i] = s_vec[y0 * 32 + x] * (1.0f - wy) + s_vec[y1 * 32 + x] * wy;
    }
    __syncthreads();

    const float* sal = feat;  // channel 0
    float* o = out + (size_t)pt * (MM * MM) + (size_t)r0 * MM;
    int h2 = h >> 1, w2 = w >> 1;

    // 2048 outputs / 256 threads = 8 independent iterations
#pragma unroll
    for (int k = 0; k < 8; k++) {
        int i = k * 256 + threadIdx.x;
        int rl = i >> 7;
        int c  = i & 127;
        int r  = r0 + rl;
        float sx = ((float)c + 0.5f) * 32.0f / wf - 0.5f;
        sx = fminf(fmaxf(sx, 0.0f), 31.0f);
        int x0 = (int)floorf(sx);
        int x1 = min(x0 + 1, 31);
        float wx = sx - (float)x0;
        float v = s_rows[rl * 32 + x0] * (1.0f - wx) +
                  s_rows[rl * 32 + x1] * wx;
        float lv = 1.0f / (1.0f + __expf(-v));
        int gr = py - h2 + r;
        int gc = px - w2 + c;
        bool valid = (r < h) && (c < w) &&
                     (gr >= 0) && (gr < HH) && (gc >= 0) && (gc < WW);
        float s = valid ? sal[gr * WW + gc] : 0.0f;
        o[i] = valid ? lv * s : 0.0f;
    }
}

extern "C" void kernel_launch(void* const* d_in, const int* in_sizes, int n_in,
                              void* d_out, int out_size) {
    const float* feat = (const float*)d_in[0];
    float* out = (float*)d_out;
    argmax_kernel<<<NPTS * BLKS_PER_HM, 256>>>(feat);
    dim3 g(NPTS, 8);
    compute_kernel<<<g, 256>>>(feat, out);
}

// round 4
// speedup vs baseline: 2.6901x; 1.1462x over previous
#include <cuda_runtime.h>
#include <math.h>

#define HH 512
#define WW 512
#define PLANE (512*512)
#define SHAPE_OFF (1*PLANE)
#define SIZE_OFF  (1025*PLANE)
#define HEAT_OFF  (1027*PLANE)
#define NPTS 10
#define MM 128
#define BLKS_PER_HM 64

// per-block partial argmax results; every slot written every run -> no init
__device__ unsigned long long g_partial[NPTS][BLKS_PER_HM];

__device__ __forceinline__ unsigned int fkey(float v) {
    unsigned int b = __float_as_uint(v);
    return (b & 0x80000000u) ? ~b : (b | 0x80000000u);
}

__device__ __forceinline__ unsigned long long umax64(unsigned long long a,
                                                     unsigned long long b) {
    return a > b ? a : b;
}

// 640 blocks (64/heatmap) x 256 threads; 16 floats/thread via float4.
__global__ void argmax_kernel(const float* __restrict__ feat) {
    int hm    = blockIdx.x >> 6;
    int chunk = blockIdx.x & 63;
    const float* heat = feat + HEAT_OFF + (size_t)hm * PLANE;
    int base = chunk * 4096;

    unsigned long long best = 0ULL;
#pragma unroll
    for (int j = 0; j < 4; j++) {
        int e = base + ((j * 256 + threadIdx.x) << 2);
        float4 v = *reinterpret_cast<const float4*>(heat + e);
        float vals[4] = {v.x, v.y, v.z, v.w};
#pragma unroll
        for (int m = 0; m < 4; m++) {
            unsigned long long p =
                ((unsigned long long)fkey(vals[m]) << 32) |
                (unsigned int)(~(unsigned int)(e + m));
            best = umax64(best, p);
        }
    }

#pragma unroll
    for (int off = 16; off > 0; off >>= 1)
        best = umax64(best, __shfl_xor_sync(0xFFFFFFFFu, best, off));

    __shared__ unsigned long long s[8];
    if ((threadIdx.x & 31) == 0) s[threadIdx.x >> 5] = best;
    __syncthreads();
    if (threadIdx.x < 32) {
        unsigned long long v = (threadIdx.x < 8) ? s[threadIdx.x] : 0ULL;
#pragma unroll
        for (int off = 4; off > 0; off >>= 1)
            v = umax64(v, __shfl_xor_sync(0xFFFFFFFFu, v, off));
        if (threadIdx.x == 0) g_partial[hm][chunk] = v;
    }
}

// grid (NPTS, MM): one block per output row, 128 threads = one element each.
__global__ void compute_kernel(const float* __restrict__ feat,
                               float* __restrict__ out) {
    __shared__ unsigned long long s_red[64];
    __shared__ float s_row[32];   // y-interpolated row (32 cols)

    int pt = blockIdx.x;
    int r  = blockIdx.y;
    int c  = threadIdx.x;

    // reduce 64 partials (L2-resident, duplicated across blocks - cheap)
    if (threadIdx.x < 64) s_red[threadIdx.x] = g_partial[pt][threadIdx.x];
    __syncthreads();
    if (threadIdx.x < 32) {
        unsigned long long v = umax64(s_red[threadIdx.x], s_red[threadIdx.x + 32]);
#pragma unroll
        for (int off = 16; off > 0; off >>= 1)
            v = umax64(v, __shfl_xor_sync(0xFFFFFFFFu, v, off));
        if (threadIdx.x == 0) s_red[0] = v;
    }
    __syncthreads();

    int idx = (int)(~(unsigned int)(s_red[0] & 0xFFFFFFFFu));
    int py = idx >> 9;
    int px = idx & 511;
    int pbase = py * WW + px;

    float hv = fabsf(feat[SIZE_OFF + pbase]);
    float wv = fabsf(feat[SIZE_OFF + PLANE + pbase]);
    int h = min(max((int)hv, 1), MM);
    int w = min(max((int)wv, 1), MM);
    float hf = (float)h, wf = (float)w;

    // y-coordinate for this row (uniform over block)
    float sy = ((float)r + 0.5f) * 32.0f / hf - 0.5f;
    sy = fminf(fmaxf(sy, 0.0f), 31.0f);
    int y0 = (int)floorf(sy);
    int y1 = min(y0 + 1, 31);
    float wy = sy - (float)y0;

    // gather only the 2 needed vec rows (64 scattered channels)
    if (threadIdx.x < 32) {
        int x = threadIdx.x;
        float v0 = feat[SHAPE_OFF + (size_t)(y0 * 32 + x) * PLANE + pbase];
        float v1 = feat[SHAPE_OFF + (size_t)(y1 * 32 + x) * PLANE + pbase];
        s_row[x] = v0 * (1.0f - wy) + v1 * wy;
    }
    __syncthreads();

    float sx = ((float)c + 0.5f) * 32.0f / wf - 0.5f;
    sx = fminf(fmaxf(sx, 0.0f), 31.0f);
    int x0 = (int)floorf(sx);
    int x1 = min(x0 + 1, 31);
    float wx = sx - (float)x0;
    float v = s_row[x0] * (1.0f - wx) + s_row[x1] * wx;
    float lv = 1.0f / (1.0f + __expf(-v));

    int gr = py - (h >> 1) + r;
    int gc = px - (w >> 1) + c;
    bool valid = (r < h) && (c < w) &&
                 (gr >= 0) && (gr < HH) && (gc >= 0) && (gc < WW);
    float s = valid ? feat[gr * WW + gc] : 0.0f;
    out[(size_t)pt * (MM * MM) + (size_t)r * MM + c] = valid ? lv * s : 0.0f;
}

extern "C" void kernel_launch(void* const* d_in, const int* in_sizes, int n_in,
                              void* d_out, int out_size) {
    const float* feat = (const float*)d_in[0];
    float* out = (float*)d_out;
    argmax_kernel<<<NPTS * BLKS_PER_HM, 256>>>(feat);
    dim3 g(NPTS, MM);
    compute_kernel<<<g, MM>>>(feat, out);
}